// round 17
// baseline (speedup 1.0000x reference)
#include <cuda_runtime.h>
#include <cuda_fp16.h>
#include <math.h>
#include <stdint.h>

// ---------------- problem constants ----------------
#define NF      32
#define C       64
#define H       96
#define W       96
#define FEAT    2304
#define DIM     768
#define M_TOK   (NF*256)                    // 8192
#define TOK_ELEMS   (M_TOK*DIM)
#define FRAME_STRIDE (C*H*W)

__device__ __forceinline__ float gelu_exact(float x){
    return 0.5f*x*(1.0f + erff(x*0.7071067811865476f));
}
__device__ __forceinline__ void mma_f16(float* d, const uint32_t* a, const uint32_t* b){
    asm volatile(
        "mma.sync.aligned.m16n8k16.row.col.f32.f16.f16.f32 "
        "{%0,%1,%2,%3}, {%4,%5,%6,%7}, {%8,%9}, {%0,%1,%2,%3};"
        : "+f"(d[0]), "+f"(d[1]), "+f"(d[2]), "+f"(d[3])
        : "r"(a[0]), "r"(a[1]), "r"(a[2]), "r"(a[3]), "r"(b[0]), "r"(b[1]));
}
__device__ __forceinline__ void cp16(uint32_t saddr, const void* g){
    asm volatile("cp.async.cg.shared.global [%0], [%1], 16;" :: "r"(saddr), "l"(g));
}
// 4-byte cp.async with zero-fill when sz==0
__device__ __forceinline__ void cp4z(uint32_t saddr, const void* g, uint32_t sz){
    asm volatile("cp.async.ca.shared.global [%0], [%1], 4, %2;"
                 :: "r"(saddr), "l"(g), "r"(sz));
}
__device__ __forceinline__ uint32_t packh2(__half a, __half b){
    uint32_t lo = (uint32_t)__half_as_ushort(a);
    uint32_t hi = (uint32_t)__half_as_ushort(b);
    return (hi << 16) | lo;
}
__device__ __forceinline__ uint32_t smem_u32(const void* p){
    return (uint32_t)__cvta_generic_to_shared(p);
}

// ---------------- device globals ----------------
__device__ uint32_t g_wf[9*4*8*64];        // conv weights fp16x2 [tap][cg][ci-pair][co]
__device__ float g_bnscale[64];
__device__ float g_bnshift[64];
__device__ uint32_t g_xp[(long)NF*32*H*W]; // x as fp16 ci-pairs [frame][cpair][y][x]
__device__ __half g_w16[DIM*FEAT];         // proj_w fp16
__device__ __half g_a16[(long)M_TOK*FEAT]; // masked patches fp16

// =====================================================================
// Kernel 0: x -> fp16 ci-pair repack, conv weights, BN fold, proj_w cvt
// =====================================================================
#define XP_ELEMS ((long)NF*32*H*W)         // 9,437,184

__global__ void prep_kernel(const float* __restrict__ x,
                            const float* __restrict__ cw,
                            const float* __restrict__ cb,
                            const float* __restrict__ gamma,
                            const float* __restrict__ beta,
                            const float* __restrict__ mean,
                            const float* __restrict__ var,
                            const float* __restrict__ pw)
{
    long idx = (long)blockIdx.x*256 + threadIdx.x;
    if (idx < XP_ELEMS){
        long px_ = idx % (H*W);
        long t   = idx / (H*W);
        int cp   = (int)(t & 31);
        int f    = (int)(t >> 5);
        long base = (long)(f*C + 2*cp)*(H*W) + px_;
        g_xp[idx] = packh2(__float2half_rn(x[base]),
                           __float2half_rn(x[base + H*W]));
    }
    if (idx < 9*4*8*64){
        int i = (int)idx;
        int co  = i & 63;
        int c   = (i >> 6) & 7;
        int cg  = (i >> 9) & 3;
        int tap = i >> 11;
        int ci0 = cg*16 + 2*c;
        g_wf[i] = packh2(__float2half_rn(cw[(co*64 + ci0)*9 + tap]),
                         __float2half_rn(cw[(co*64 + ci0 + 1)*9 + tap]));
    }
    if (idx < DIM*FEAT)
        g_w16[idx] = __float2half_rn(pw[idx]);
    if (idx < 64){
        int co = (int)idx;
        float s = gamma[co] * rsqrtf(var[co] + 1e-5f);
        g_bnscale[co] = s;
        g_bnshift[co] = (cb[co] - mean[co]) * s + beta[co];
    }
}

// =====================================================================
// Kernel 1: conv3x3 implicit GEMM, fp16 mma, 16 acc chains per warp
// (tile 256px x 64co, warp 64x32, mt=4). ALL staging via cp.async
// (halo from pre-paired g_xp with zfill padding) -> minimal registers,
// sw-pipelined double buffer, 1 barrier per cg.
// =====================================================================
#define CV_SX 2880                 // u32/buffer: 8c x 18y x 20x (stride 360)
#define CV_SB (9*8*72)             // u32/buffer: 2592
#define CV_SMEM_BYTES ((2*CV_SX + 2*CV_SB)*4)   // 43,776

__global__ __launch_bounds__(256, 2) void conv_mma_kernel(
    const float* __restrict__ mask,
    float* __restrict__ out_patches)
{
    extern __shared__ __align__(16) uint32_t dynsm[];
    uint32_t* s_x = dynsm;                     // [buf][c*360 + y*20 + x]
    uint32_t* s_b = dynsm + 2*CV_SX;           // [buf][(tap*8+c)*72 + co]

    __shared__ float s_mask[36];
    __shared__ float s_scale[64], s_shift[64];

    const int tid  = threadIdx.x;
    const int lane = tid & 31;
    const int wid  = tid >> 5;
    const int wm   = wid & 3;
    const int wn   = wid >> 2;
    const int lg   = lane >> 2;      // 0..7
    const int lt   = lane & 3;       // 0..3

    const int w0    = blockIdx.x * 16;
    const int h0    = blockIdx.y * 16;
    const int frame = blockIdx.z;

    if (tid < 36) s_mask[tid] = mask[tid];
    if (tid < 64){ s_scale[tid] = g_bnscale[tid]; s_shift[tid] = g_bnshift[tid]; }

    // ---- staging lambdas (all cp.async; no registers held) ----
    auto issueB = [&](uint32_t* dst, int cg){
        for (int i = tid; i < 1152; i += 256){
            int q   = i & 15;
            int row = i >> 4;            // 0..71 = tap*8 + c
            int tap = row >> 3, c = row & 7;
            cp16(smem_u32(dst + row*72 + q*4),
                 g_wf + (((long)(tap*4 + cg)*8 + c)*64 + q*4));
        }
    };
    auto issueHalo = [&](uint32_t* dst, int cg){
        const long fb = ((long)frame*32 + cg*8);
        for (int i = tid; i < 2880; i += 256){
            int c   = i / 360;
            int rem = i - c*360;
            int y   = rem / 20;
            int xx  = rem - y*20;
            int gy  = h0 + y - 1;
            int gx  = w0 + xx - 1;
            bool ok = (gy >= 0) && (gy < H) && (gx >= 0) && (gx < W);
            int cgy = ok ? gy : 0;
            int cgx = ok ? gx : 0;
            cp4z(smem_u32(dst + i),
                 g_xp + ((fb + c)*H + cgy)*W + cgx,
                 ok ? 4u : 0u);
        }
    };

    float acc[4][4][4];
    #pragma unroll
    for (int mt=0;mt<4;mt++)
        #pragma unroll
        for (int nt=0;nt<4;nt++)
            #pragma unroll
            for (int r=0;r<4;r++) acc[mt][nt][r] = 0.f;

    // ---- prologue: stage cg=0 into buffer 0 ----
    issueB(s_b, 0);
    issueHalo(s_x, 0);
    asm volatile("cp.async.commit_group;" ::: "memory");
    asm volatile("cp.async.wait_group 0;" ::: "memory");
    __syncthreads();

    for (int cg = 0; cg < 4; cg++){
        const int cur = cg & 1;
        const int nxt = cur ^ 1;
        const bool hasnext = (cg < 3);
        const uint32_t* px_ = s_x + cur*CV_SX;
        const uint32_t* pb_ = s_b + cur*CV_SB;

        if (hasnext){
            issueB(s_b + nxt*CV_SB, cg + 1);
            issueHalo(s_x + nxt*CV_SX, cg + 1);
            asm volatile("cp.async.commit_group;" ::: "memory");
        }

        // ---- 9 taps: 16 mma per warp-tap, no barriers ----
        #pragma unroll
        for (int tap = 0; tap < 9; tap++){
            const int ky = tap / 3, kx = tap - ky*3;
            uint32_t a[4][4], b[4][2];
            #pragma unroll
            for (int mt = 0; mt < 4; mt++){
                const int py = wm*4 + mt + ky;
                const int pxi = lg + kx;
                const int b0 = lt*360     + py*20 + pxi;
                const int b1 = (lt+4)*360 + py*20 + pxi;
                a[mt][0] = px_[b0];
                a[mt][1] = px_[b0 + 8];
                a[mt][2] = px_[b1];
                a[mt][3] = px_[b1 + 8];
            }
            #pragma unroll
            for (int nt = 0; nt < 4; nt++){
                const int co = wn*32 + nt*8 + lg;
                b[nt][0] = pb_[(tap*8 + lt  )*72 + co];
                b[nt][1] = pb_[(tap*8 + lt+4)*72 + co];
            }
            #pragma unroll
            for (int mt = 0; mt < 4; mt++)
                #pragma unroll
                for (int nt = 0; nt < 4; nt++)
                    mma_f16(acc[mt][nt], a[mt], b[nt]);
        }

        if (hasnext){
            asm volatile("cp.async.wait_group 0;" ::: "memory");
            __syncthreads();
        }
    }

    // ---- epilogue: BN + GELU + mask -> patches (fp32) + fp16 A copy ----
    #pragma unroll
    for (int mt = 0; mt < 4; mt++){
        const int r0 = wm*64 + mt*16 + lg;
        #pragma unroll
        for (int dr = 0; dr < 2; dr++){
            const int r = r0 + dr*8;
            const int hh = h0 + (r >> 4);
            const int ww = w0 + (r & 15);
            const int l = hh / 6, i_in = hh - l*6;
            const int rr = ww / 6, j_in = ww - rr*6;
            const float mk = s_mask[i_in*6 + j_in];
            const long arow = ((long)frame*256 + l*16 + rr)*FEAT;
            #pragma unroll
            for (int nt = 0; nt < 4; nt++){
                const int c0 = wn*32 + nt*8 + (lt << 1);
                #pragma unroll
                for (int dc = 0; dc < 2; dc++){
                    const int co = c0 + dc;
                    const float v = acc[mt][nt][dr*2 + dc];
                    float o = gelu_exact(v*s_scale[co] + s_shift[co]) * mk;
                    const long k = arow + co*36 + i_in*6 + j_in;
                    out_patches[k] = o;
                    g_a16[k] = __float2half_rn(o);
                }
            }
        }
    }
}

// =====================================================================
// Kernel 2: tokens GEMM, fp16 m16n8k16, 32x48 warp tile
// (round-15 kernel, known good, unchanged)
// =====================================================================
#define GBM 128
#define GBN 96
#define GBK 64
#define KSTR 36
#define STAGES 3
#define SA_WORDS (GBM*KSTR)
#define SB_WORDS (GBN*KSTR)
#define GEMM_SMEM_BYTES ((STAGES*(SA_WORDS+SB_WORDS))*4)   // 96768

__global__ __launch_bounds__(256, 2) void gemm_tokens_f16_kernel(
    const float* __restrict__ bias,
    float* __restrict__ tok)
{
    extern __shared__ uint32_t smdyn[];
    uint32_t* s_a = smdyn;
    uint32_t* s_b = smdyn + STAGES*SA_WORDS;
    const uint32_t sa_base = smem_u32(s_a);
    const uint32_t sb_base = smem_u32(s_b);

    const int tid  = threadIdx.x;
    const int lane = tid & 31;
    const int wid  = tid >> 5;
    const int wm   = wid & 3;
    const int wn   = wid >> 2;
    const int bm   = blockIdx.y;
    const int bn   = blockIdx.x;

    const __half* Ab = g_a16 + (long)bm*GBM*FEAT;
    const __half* Bb = g_w16 + (long)bn*GBN*FEAT;

    float acc[2][6][4];
    #pragma unroll
    for (int mt=0;mt<2;mt++)
        #pragma unroll
        for (int nt=0;nt<6;nt++)
            #pragma unroll
            for (int r=0;r<4;r++) acc[mt][nt][r] = 0.f;

    const int crowA = tid >> 3;
    const int ck4   = (tid & 7) << 2;
    const int ckh   = ck4 << 1;

    #pragma unroll
    for (int st = 0; st < 2; st++){
        const int kg = st*GBK;
        #pragma unroll
        for (int j = 0; j < 4; j++){
            int row = crowA + j*32;
            cp16(sa_base + (uint32_t)((st*GBM + row)*KSTR + ck4)*4,
                 Ab + (long)row*FEAT + kg + ckh);
        }
        #pragma unroll
        for (int j = 0; j < 3; j++){
            int row = crowA + j*32;
            cp16(sb_base + (uint32_t)((st*GBN + row)*KSTR + ck4)*4,
                 Bb + (long)row*FEAT + kg + ckh);
        }
        asm volatile("cp.async.commit_group;");
    }
    asm volatile("cp.async.wait_group 1;");
    __syncthreads();

    const int NKT = FEAT / GBK;   // 36
    for (int kt = 0; kt < NKT; kt++){
        const int cur = kt % STAGES;
        if (kt + 2 < NKT){
            const int st = (kt + 2) % STAGES;
            const int kg = (kt + 2)*GBK;
            #pragma unroll
            for (int j = 0; j < 4; j++){
                int row = crowA + j*32;
                cp16(sa_base + (uint32_t)((st*GBM + row)*KSTR + ck4)*4,
                     Ab + (long)row*FEAT + kg + ckh);
            }
            #pragma unroll
            for (int j = 0; j < 3; j++){
                int row = crowA + j*32;
                cp16(sb_base + (uint32_t)((st*GBN + row)*KSTR + ck4)*4,
                     Bb + (long)row*FEAT + kg + ckh);
            }
        }
        asm volatile("cp.async.commit_group;");

        const uint32_t* pa = s_a + cur*SA_WORDS;
        const uint32_t* pb = s_b + cur*SB_WORDS;
        #pragma unroll
        for (int ks = 0; ks < 4; ks++){
            const int kb = ks*8 + (lane & 3);
            uint32_t af[2][4], bf[6][2];
            #pragma unroll
            for (int mt=0;mt<2;mt++){
                int r0 = wm*32 + mt*16 + (lane >> 2);
                af[mt][0] = pa[r0*KSTR + kb];
                af[mt][1] = pa[(r0+8)*KSTR + kb];
                af[mt][2] = pa[r0*KSTR + kb + 4];
                af[mt][3] = pa[(r0+8)*KSTR + kb + 4];
            }
            #pragma unroll
            for (int nt=0;nt<6;nt++){
                int c0 = wn*48 + nt*8 + (lane >> 2);
                bf[nt][0] = pb[c0*KSTR + kb];
                bf[nt][1] = pb[c0*KSTR + kb + 4];
            }
            #pragma unroll
            for (int mt=0;mt<2;mt++)
                #pragma unroll
                for (int nt=0;nt<6;nt++)
                    mma_f16(acc[mt][nt], af[mt], bf[nt]);
        }

        asm volatile("cp.async.wait_group 1;");
        __syncthreads();
    }

    #pragma unroll
    for (int mt=0;mt<2;mt++){
        const int r0 = bm*GBM + wm*32 + mt*16 + (lane >> 2);
        #pragma unroll
        for (int nt=0;nt<6;nt++){
            const int c0 = bn*GBN + wn*48 + nt*8 + ((lane & 3) << 1);
            float2 b2 = *(const float2*)(bias + c0);
            float2 o0, o1;
            o0.x = gelu_exact(acc[mt][nt][0] + b2.x);
            o0.y = gelu_exact(acc[mt][nt][1] + b2.y);
            o1.x = gelu_exact(acc[mt][nt][2] + b2.x);
            o1.y = gelu_exact(acc[mt][nt][3] + b2.y);
            *(float2*)(tok + (long)r0*DIM + c0)     = o0;
            *(float2*)(tok + (long)(r0+8)*DIM + c0) = o1;
        }
    }
}

// =====================================================================
extern "C" void kernel_launch(void* const* d_in, const int* in_sizes, int n_in,
                              void* d_out, int out_size)
{
    const float* x      = (const float*)d_in[0];
    const float* conv_w = (const float*)d_in[1];
    const float* conv_b = (const float*)d_in[2];
    const float* gamma  = (const float*)d_in[3];
    const float* beta   = (const float*)d_in[4];
    const float* mean   = (const float*)d_in[5];
    const float* var    = (const float*)d_in[6];
    const float* proj_w = (const float*)d_in[7];
    const float* proj_b = (const float*)d_in[8];
    const float* mask   = (const float*)d_in[9];

    float* tokens  = (float*)d_out;                 // [8192, 768]
    float* patches = (float*)d_out + TOK_ELEMS;     // [8192, 2304]

    cudaFuncSetAttribute(conv_mma_kernel,
                         cudaFuncAttributeMaxDynamicSharedMemorySize,
                         CV_SMEM_BYTES);
    cudaFuncSetAttribute(gemm_tokens_f16_kernel,
                         cudaFuncAttributeMaxDynamicSharedMemorySize,
                         GEMM_SMEM_BYTES);

    // 0) prep: x fp16 ci-pair repack + conv weights + BN + proj_w cvt
    {
        long blocks = (XP_ELEMS + 255) / 256;   // 36,864
        prep_kernel<<<(unsigned)blocks, 256>>>(x, conv_w, conv_b, gamma, beta,
                                               mean, var, proj_w);
    }

    // 1) conv implicit GEMM (16 chains/warp, all-cp.async staging)
    {
        dim3 grid(W/16, H/16, NF);   // 6 x 6 x 32 = 1152
        conv_mma_kernel<<<grid, 256, CV_SMEM_BYTES>>>(mask, patches);
    }

    // 2) projection GEMM + bias + GELU (fp16 m16n8k16, 32x48 warp tile)
    {
        dim3 grid(DIM/GBN, M_TOK/GBM);   // (8, 64)
        gemm_tokens_f16_kernel<<<grid, 256, GEMM_SMEM_BYTES>>>(proj_b, tokens);
    }
}